// round 3
// baseline (speedup 1.0000x reference)
#include <cuda_runtime.h>
#include <cuda_bf16.h>
#include <math.h>

// Problem constants
#define S_LEN 2048
#define D_DIM 768
#define N_STATE 16
#define N_HEADS 12
#define DH 64
#define WINDOW 128
#define KK 1843            // int((1-0.1)*2048)
#define SPIKE 0.1f

// ---------------------------------------------------------------------------
// Scratch (device globals; no dynamic allocation allowed)
// ---------------------------------------------------------------------------
__device__ float g_gate[S_LEN * D_DIM];
__device__ float g_H[S_LEN * D_DIM];
__device__ float g_Q[S_LEN * D_DIM];
__device__ float g_K[S_LEN * D_DIM];
__device__ float g_V[S_LEN * D_DIM];
__device__ float g_ctx[S_LEN * D_DIM];
__device__ float g_scores[(size_t)N_HEADS * S_LEN * S_LEN];   // 192 MB

// ---------------------------------------------------------------------------
// Generic tiled fp32 GEMM: C = alpha * A * op(B) (+bias) (+sigmoid)
//   BT=true : C[m,n] = sum_k A[m,k] * B[n,k]
//   BT=false: C[m,n] = sum_k A[m,k] * B[k,n]
// EPI: 0 = none, 1 = +bias, 2 = sigmoid(v + bias)
// Per-z (head) strides for batched use.
// Assumes M,N divisible by 64 and K divisible by 16.
// ---------------------------------------------------------------------------
template<bool BT, int EPI>
__global__ __launch_bounds__(256)
void gemm_kernel(const float* __restrict__ A, const float* __restrict__ B,
                 const float* __restrict__ bias, float* __restrict__ C,
                 int M, int N, int K, int lda, int ldb, int ldc,
                 long Astride, long Bstride, long Cstride, float alpha)
{
    A += (long)blockIdx.z * Astride;
    B += (long)blockIdx.z * Bstride;
    C += (long)blockIdx.z * Cstride;

    const int BM = 64, BN = 64, BK = 16;
    __shared__ float As[BK][BM + 1];
    __shared__ float Bs[BK][BN + 1];

    int tid = threadIdx.x;
    int rm = tid >> 4;        // 0..15
    int rn = tid & 15;        // 0..15
    int row0 = blockIdx.y * BM;
    int col0 = blockIdx.x * BN;

    float acc[4][4];
#pragma unroll
    for (int i = 0; i < 4; i++)
#pragma unroll
        for (int j = 0; j < 4; j++) acc[i][j] = 0.f;

    for (int k0 = 0; k0 < K; k0 += BK) {
        // Load A tile 64x16 (row-major)
#pragma unroll
        for (int i = tid; i < BM * BK; i += 256) {
            int m = i >> 4, kk = i & 15;
            As[kk][m] = A[(long)(row0 + m) * lda + (k0 + kk)];
        }
        // Load B tile
        if (BT) {
#pragma unroll
            for (int i = tid; i < BN * BK; i += 256) {
                int n = i >> 4, kk = i & 15;
                Bs[kk][n] = B[(long)(col0 + n) * ldb + (k0 + kk)];
            }
        } else {
#pragma unroll
            for (int i = tid; i < BN * BK; i += 256) {
                int kk = i >> 6, n = i & 63;
                Bs[kk][n] = B[(long)(k0 + kk) * ldb + (col0 + n)];
            }
        }
        __syncthreads();

#pragma unroll
        for (int kk = 0; kk < BK; ++kk) {
            float a[4], b[4];
#pragma unroll
            for (int i = 0; i < 4; i++) a[i] = As[kk][rm * 4 + i];
#pragma unroll
            for (int j = 0; j < 4; j++) b[j] = Bs[kk][rn * 4 + j];
#pragma unroll
            for (int i = 0; i < 4; i++)
#pragma unroll
                for (int j = 0; j < 4; j++) acc[i][j] = fmaf(a[i], b[j], acc[i][j]);
        }
        __syncthreads();
    }

#pragma unroll
    for (int i = 0; i < 4; i++) {
#pragma unroll
        for (int j = 0; j < 4; j++) {
            int n = col0 + rn * 4 + j;
            float v = acc[i][j] * alpha;
            if (EPI >= 1) v += bias[n];
            if (EPI == 2) v = 1.f / (1.f + __expf(-v));
            C[(long)(row0 + rm * 4 + i) * ldc + n] = v;
        }
    }
}

// ---------------------------------------------------------------------------
// SSM sequential scan. 16 lanes per channel (lane = state index n).
// h_t = h_{t-1} + thresh(dt*(A h_{t-1} + x_t*B[:,d])) * gate_t[d]
// y_t[d] = sum_n h_t[n]*Cm[d,n];  Hout = x + y
// ---------------------------------------------------------------------------
__global__ __launch_bounds__(128)
void ssm_kernel(const float* __restrict__ x, const float* __restrict__ gate,
                const float* __restrict__ Amat, const float* __restrict__ Bm,
                const float* __restrict__ Cm, const float* __restrict__ log_dt,
                float* __restrict__ Hout)
{
    int lane = threadIdx.x & 15;                       // state index n
    int d = blockIdx.x * (blockDim.x >> 4) + (threadIdx.x >> 4);
    if (d >= D_DIM) return;

    float Arow[N_STATE];
#pragma unroll
    for (int m = 0; m < N_STATE; m++) Arow[m] = Amat[lane * N_STATE + m];
    float Bn  = Bm[lane * D_DIM + d];
    float Cn  = Cm[d * N_STATE + lane];
    float dtd = fminf(fmaxf(expf(log_dt[d]), 1e-3f), 1e-1f);

    float h = 0.f;
    for (int t = 0; t < S_LEN; t++) {
        float xv = __ldg(&x[t * D_DIM + d]);
        float g  = __ldg(&gate[t * D_DIM + d]);
        float acc = 0.f;
#pragma unroll
        for (int m = 0; m < N_STATE; m++)
            acc = fmaf(Arow[m], __shfl_sync(0xffffffffu, h, m, 16), acc);
        float sc = (acc + xv * Bn) * dtd;
        if (fabsf(sc) > SPIKE) h = fmaf(sc, g, h);
        float p = h * Cn;
#pragma unroll
        for (int off = 8; off; off >>= 1)
            p += __shfl_xor_sync(0xffffffffu, p, off, 16);
        if (lane == 0) Hout[t * D_DIM + d] = xv + p;
    }
}

// ---------------------------------------------------------------------------
// Per-row: radix-select kk-th largest |score| over the FULL row, then
// local mask (keep j <= i+WINDOW) + sparse mask (|s| >= threshold),
// softmax, write probs in place.
// One block (256 threads) per (row i, head h).
// ---------------------------------------------------------------------------
__global__ __launch_bounds__(256)
void mask_softmax_kernel(float* __restrict__ scores)
{
    int i  = blockIdx.x;        // query row
    int hd = blockIdx.y;        // head
    float* row = scores + ((size_t)hd * S_LEN + i) * S_LEN;

    __shared__ float srow[S_LEN];
    __shared__ int   hist[256];
    __shared__ int   sh_sel[2];
    __shared__ float red[256];

    int tid = threadIdx.x;
    for (int j = tid; j < S_LEN; j += 256) srow[j] = row[j];
    __syncthreads();

    // --- radix select: find bit pattern T of the KK-th largest |s| ---
    unsigned prefix = 0;
    int kneed = KK;
#pragma unroll
    for (int byte = 3; byte >= 0; --byte) {
        hist[tid] = 0;
        __syncthreads();
        unsigned pm = (byte == 3) ? 0u : (0xFFFFFFFFu << (8 * (byte + 1)));
        for (int j = tid; j < S_LEN; j += 256) {
            unsigned bits = __float_as_uint(fabsf(srow[j]));
            if ((bits & pm) == prefix)
                atomicAdd(&hist[(bits >> (8 * byte)) & 255], 1);
        }
        __syncthreads();
        if (tid == 0) {
            int c = 0, sel = 0, kn = kneed;
            for (int b = 255; b >= 0; --b) {
                c += hist[b];
                if (c >= kn) { sel = b; kn -= (c - hist[b]); break; }
            }
            sh_sel[0] = sel; sh_sel[1] = kn;
        }
        __syncthreads();
        prefix |= ((unsigned)sh_sel[0]) << (8 * byte);
        kneed = sh_sel[1];
        __syncthreads();
    }
    unsigned T = prefix;

    // --- apply masks, compute max ---
    int jmax = i + WINDOW;
    float m = -INFINITY;
    for (int j = tid; j < S_LEN; j += 256) {
        float s = srow[j];
        bool keep = (j <= jmax) && (__float_as_uint(fabsf(s)) >= T);
        float sv = keep ? s : -INFINITY;
        srow[j] = sv;
        m = fmaxf(m, sv);
    }
    red[tid] = m; __syncthreads();
#pragma unroll
    for (int st = 128; st; st >>= 1) {
        if (tid < st) red[tid] = fmaxf(red[tid], red[tid + st]);
        __syncthreads();
    }
    m = red[0];
    __syncthreads();

    // --- exp + sum ---
    float z = 0.f;
    for (int j = tid; j < S_LEN; j += 256) {
        float s = srow[j];
        float e = (s == -INFINITY) ? 0.f : __expf(s - m);
        srow[j] = e;
        z += e;
    }
    red[tid] = z; __syncthreads();
#pragma unroll
    for (int st = 128; st; st >>= 1) {
        if (tid < st) red[tid] += red[tid + st];
        __syncthreads();
    }
    z = red[0];
    float inv = (z > 0.f) ? 1.f / z : 0.f;
    for (int j = tid; j < S_LEN; j += 256) row[j] = srow[j] * inv;
}

// ---------------------------------------------------------------------------
// Launch
// ---------------------------------------------------------------------------
extern "C" void kernel_launch(void* const* d_in, const int* in_sizes, int n_in,
                              void* d_out, int out_size)
{
    const float* x      = (const float*)d_in[0];
    const float* Amat   = (const float*)d_in[1];
    const float* Bm     = (const float*)d_in[2];
    const float* Cm     = (const float*)d_in[3];
    const float* log_dt = (const float*)d_in[4];
    const float* Wg = (const float*)d_in[5];  const float* bg = (const float*)d_in[6];
    const float* Wq = (const float*)d_in[7];  const float* bq = (const float*)d_in[8];
    const float* Wk = (const float*)d_in[9];  const float* bk = (const float*)d_in[10];
    const float* Wv = (const float*)d_in[11]; const float* bv = (const float*)d_in[12];
    const float* Wd = (const float*)d_in[13]; const float* bd = (const float*)d_in[14];
    float* out = (float*)d_out;

    float *gate, *H, *Q, *K, *V, *ctx, *scores;
    cudaGetSymbolAddress((void**)&gate,   g_gate);
    cudaGetSymbolAddress((void**)&H,      g_H);
    cudaGetSymbolAddress((void**)&Q,      g_Q);
    cudaGetSymbolAddress((void**)&K,      g_K);
    cudaGetSymbolAddress((void**)&V,      g_V);
    cudaGetSymbolAddress((void**)&ctx,    g_ctx);
    cudaGetSymbolAddress((void**)&scores, g_scores);

    dim3 blk(256);

    // 1) gate = sigmoid(X Wg^T + bg)
    {
        dim3 grid(D_DIM / 64, S_LEN / 64, 1);
        gemm_kernel<true, 2><<<grid, blk>>>(x, Wg, bg, gate,
            S_LEN, D_DIM, D_DIM, D_DIM, D_DIM, D_DIM, 0, 0, 0, 1.f);
    }
    // 2) SSM scan -> H = x + y
    {
        ssm_kernel<<<D_DIM / 8, 128>>>(x, gate, Amat, Bm, Cm, log_dt, H);
    }
    // 3) Q, K, V projections from H
    {
        dim3 grid(D_DIM / 64, S_LEN / 64, 1);
        gemm_kernel<true, 1><<<grid, blk>>>(H, Wq, bq, Q,
            S_LEN, D_DIM, D_DIM, D_DIM, D_DIM, D_DIM, 0, 0, 0, 1.f);
        gemm_kernel<true, 1><<<grid, blk>>>(H, Wk, bk, K,
            S_LEN, D_DIM, D_DIM, D_DIM, D_DIM, D_DIM, 0, 0, 0, 1.f);
        gemm_kernel<true, 1><<<grid, blk>>>(H, Wv, bv, V,
            S_LEN, D_DIM, D_DIM, D_DIM, D_DIM, D_DIM, 0, 0, 0, 1.f);
    }
    // 4) scores[h] = Q_h K_h^T / 8
    {
        dim3 grid(S_LEN / 64, S_LEN / 64, N_HEADS);
        gemm_kernel<true, 0><<<grid, blk>>>(Q, K, nullptr, scores,
            S_LEN, S_LEN, DH, D_DIM, D_DIM, S_LEN,
            DH, DH, (long)S_LEN * S_LEN, 0.125f);
    }
    // 5) per-row top-k select + masks + softmax (in place)
    {
        dim3 grid(S_LEN, N_HEADS);
        mask_softmax_kernel<<<grid, blk>>>(scores);
    }
    // 6) ctx[h] = P_h V_h
    {
        dim3 grid(DH / 64, S_LEN / 64, N_HEADS);
        gemm_kernel<false, 0><<<grid, blk>>>(scores, V, nullptr, ctx,
            S_LEN, DH, S_LEN, S_LEN, D_DIM, D_DIM,
            (long)S_LEN * S_LEN, DH, DH, 1.f);
    }
    // 7) out = ctx Wd^T + bd
    {
        dim3 grid(D_DIM / 64, S_LEN / 64, 1);
        gemm_kernel<true, 1><<<grid, blk>>>(ctx, Wd, bd, out,
            S_LEN, D_DIM, D_DIM, D_DIM, D_DIM, D_DIM, 0, 0, 0, 1.f);
    }
}

// round 4
// speedup vs baseline: 1.3641x; 1.3641x over previous
#include <cuda_runtime.h>
#include <cuda_bf16.h>
#include <math.h>
#include <stdint.h>

// Problem constants
#define S_LEN 2048
#define D_DIM 768
#define N_STATE 16
#define N_HEADS 12
#define DH 64
#define WINDOW 128
#define KK 1843            // int((1-0.1)*2048)
#define SPIKE 0.1f

// ---------------------------------------------------------------------------
// Scratch (device globals; no dynamic allocation allowed)
// ---------------------------------------------------------------------------
__device__ float g_gate[S_LEN * D_DIM];
__device__ float g_H[S_LEN * D_DIM];
__device__ float g_Q[S_LEN * D_DIM];
__device__ float g_K[S_LEN * D_DIM];
__device__ float g_V[S_LEN * D_DIM];
__device__ float g_ctx[S_LEN * D_DIM];
__device__ float g_scores[(size_t)N_HEADS * S_LEN * S_LEN];   // 192 MB

// ---------------------------------------------------------------------------
// Split-TF32 helpers (3-MMA emulation of fp32 GEMM on tensor cores)
// ---------------------------------------------------------------------------
__device__ __forceinline__ void split_tf32(float a, uint32_t& hi, uint32_t& lo) {
    asm("cvt.rna.tf32.f32 %0, %1;" : "=r"(hi) : "f"(a));
    float r = a - __uint_as_float(hi);
    asm("cvt.rna.tf32.f32 %0, %1;" : "=r"(lo) : "f"(r));
}

__device__ __forceinline__ void mma8(float c[4], const uint32_t a[4], const uint32_t b[2]) {
    asm("mma.sync.aligned.m16n8k8.row.col.f32.tf32.tf32.f32 "
        "{%0,%1,%2,%3},{%4,%5,%6,%7},{%8,%9},{%0,%1,%2,%3};"
        : "+f"(c[0]), "+f"(c[1]), "+f"(c[2]), "+f"(c[3])
        : "r"(a[0]), "r"(a[1]), "r"(a[2]), "r"(a[3]), "r"(b[0]), "r"(b[1]));
}

// ---------------------------------------------------------------------------
// Tensor-core GEMM (split tf32, ~fp32 accuracy):
//   BT=true : C[m,n] = alpha * sum_k A[m,k]*B[n,k]  (+bias) (+sigmoid)
//   BT=false: C[m,n] = alpha * sum_k A[m,k]*B[k,n]
// Tiles: BM=128, BN=64, BK=32. 256 threads, 8 warps (4 m x 2 n), 32x32/warp.
// band>0: limit k-range to row0+band (banded A, e.g. windowed P in PV).
// Requires: M%128==0, N%64==0, K%32==0, pointers 16B aligned.
// ---------------------------------------------------------------------------
template<bool BT, int EPI>
__global__ __launch_bounds__(256)
void gemm_tc(const float* __restrict__ A, const float* __restrict__ B,
             const float* __restrict__ bias, float* __restrict__ C,
             int M, int N, int K, int lda, int ldb, int ldc,
             long Astride, long Bstride, long Cstride, float alpha, int band)
{
    A += (long)blockIdx.z * Astride;
    B += (long)blockIdx.z * Bstride;
    C += (long)blockIdx.z * Cstride;

    const int BM = 128, BN = 64, BK = 32, LD = BK + 4;   // padded stride 36
    __shared__ float As[BM * LD];   // 18 KB
    __shared__ float Bs[BN * LD];   // 9 KB

    int tid  = threadIdx.x;
    int lane = tid & 31;
    int wid  = tid >> 5;
    int wm   = wid >> 1;            // 0..3
    int wn   = wid & 1;             // 0..1
    int g    = lane >> 2;           // groupID 0..7
    int tg   = lane & 3;            // thread-in-group

    int row0 = blockIdx.y * BM;
    int col0 = blockIdx.x * BN;

    float c[2][4][4];
#pragma unroll
    for (int mi = 0; mi < 2; mi++)
#pragma unroll
        for (int ni = 0; ni < 4; ni++)
#pragma unroll
            for (int r = 0; r < 4; r++) c[mi][ni][r] = 0.f;

    int Keff = band > 0 ? min(K, row0 + band) : K;

    for (int k0 = 0; k0 < Keff; k0 += BK) {
        // ---- load A tile (128 x 32), vectorized ----
#pragma unroll
        for (int i = 0; i < 4; i++) {
            int idx = tid + i * 256;           // 1024 float4s
            int m = idx >> 3, kc = (idx & 7) << 2;
            float4 v = *(const float4*)&A[(long)(row0 + m) * lda + (k0 + kc)];
            *(float4*)&As[m * LD + kc] = v;
        }
        // ---- load B tile into Bs[n][k] ----
        if (BT) {
#pragma unroll
            for (int i = 0; i < 2; i++) {
                int idx = tid + i * 256;       // 512 float4s
                int n = idx >> 3, kc = (idx & 7) << 2;
                float4 v = *(const float4*)&B[(long)(col0 + n) * ldb + (k0 + kc)];
                *(float4*)&Bs[n * LD + kc] = v;
            }
        } else {
#pragma unroll
            for (int i = 0; i < 8; i++) {
                int idx = tid + i * 256;       // 2048 scalars
                int kk = idx >> 6, n = idx & 63;
                Bs[n * LD + kk] = B[(long)(k0 + kk) * ldb + (col0 + n)];
            }
        }
        __syncthreads();

#pragma unroll
        for (int ks = 0; ks < BK; ks += 8) {
            // A fragments for the 2 m-subtiles
            uint32_t ah[2][4], al[2][4];
#pragma unroll
            for (int mi = 0; mi < 2; mi++) {
                int mb = wm * 32 + mi * 16;
                float f0 = As[(mb + g)     * LD + ks + tg];
                float f1 = As[(mb + g + 8) * LD + ks + tg];
                float f2 = As[(mb + g)     * LD + ks + tg + 4];
                float f3 = As[(mb + g + 8) * LD + ks + tg + 4];
                split_tf32(f0, ah[mi][0], al[mi][0]);
                split_tf32(f1, ah[mi][1], al[mi][1]);
                split_tf32(f2, ah[mi][2], al[mi][2]);
                split_tf32(f3, ah[mi][3], al[mi][3]);
            }
            // B fragments for the 4 n-subtiles
            uint32_t bh[4][2], bl[4][2];
#pragma unroll
            for (int ni = 0; ni < 4; ni++) {
                int nb = wn * 32 + ni * 8 + g;
                float f0 = Bs[nb * LD + ks + tg];
                float f1 = Bs[nb * LD + ks + tg + 4];
                split_tf32(f0, bh[ni][0], bl[ni][0]);
                split_tf32(f1, bh[ni][1], bl[ni][1]);
            }
            // 3-MMA split accumulate
#pragma unroll
            for (int mi = 0; mi < 2; mi++)
#pragma unroll
                for (int ni = 0; ni < 4; ni++) {
                    mma8(c[mi][ni], ah[mi], bh[ni]);
                    mma8(c[mi][ni], ah[mi], bl[ni]);
                    mma8(c[mi][ni], al[mi], bh[ni]);
                }
        }
        __syncthreads();
    }

    // ---- epilogue ----
#pragma unroll
    for (int mi = 0; mi < 2; mi++) {
#pragma unroll
        for (int ni = 0; ni < 4; ni++) {
            int row = row0 + wm * 32 + mi * 16 + g;
            int col = col0 + wn * 32 + ni * 8 + 2 * tg;
            float v0 = c[mi][ni][0] * alpha;
            float v1 = c[mi][ni][1] * alpha;
            float v2 = c[mi][ni][2] * alpha;
            float v3 = c[mi][ni][3] * alpha;
            if (EPI >= 1) {
                float b0 = bias[col], b1 = bias[col + 1];
                v0 += b0; v1 += b1; v2 += b0; v3 += b1;
            }
            if (EPI == 2) {
                v0 = 1.f / (1.f + __expf(-v0));
                v1 = 1.f / (1.f + __expf(-v1));
                v2 = 1.f / (1.f + __expf(-v2));
                v3 = 1.f / (1.f + __expf(-v3));
            }
            *(float2*)&C[(long)row * ldc + col]       = make_float2(v0, v1);
            *(float2*)&C[(long)(row + 8) * ldc + col] = make_float2(v2, v3);
        }
    }
}

// ---------------------------------------------------------------------------
// SSM sequential scan. 16 lanes per channel (lane = state index n).
// ---------------------------------------------------------------------------
__global__ __launch_bounds__(128)
void ssm_kernel(const float* __restrict__ x, const float* __restrict__ gate,
                const float* __restrict__ Amat, const float* __restrict__ Bm,
                const float* __restrict__ Cm, const float* __restrict__ log_dt,
                float* __restrict__ Hout)
{
    int lane = threadIdx.x & 15;                       // state index n
    int d = blockIdx.x * (blockDim.x >> 4) + (threadIdx.x >> 4);
    if (d >= D_DIM) return;

    float Arow[N_STATE];
#pragma unroll
    for (int m = 0; m < N_STATE; m++) Arow[m] = Amat[lane * N_STATE + m];
    float Bn  = Bm[lane * D_DIM + d];
    float Cn  = Cm[d * N_STATE + lane];
    float dtd = fminf(fmaxf(expf(log_dt[d]), 1e-3f), 1e-1f);

    float h = 0.f;
    for (int t = 0; t < S_LEN; t++) {
        float xv = __ldg(&x[t * D_DIM + d]);
        float g  = __ldg(&gate[t * D_DIM + d]);
        float acc = 0.f;
#pragma unroll
        for (int m = 0; m < N_STATE; m++)
            acc = fmaf(Arow[m], __shfl_sync(0xffffffffu, h, m, 16), acc);
        float sc = (acc + xv * Bn) * dtd;
        if (fabsf(sc) > SPIKE) h = fmaf(sc, g, h);
        float p = h * Cn;
#pragma unroll
        for (int off = 8; off; off >>= 1)
            p += __shfl_xor_sync(0xffffffffu, p, off, 16);
        if (lane == 0) Hout[t * D_DIM + d] = xv + p;
    }
}

// ---------------------------------------------------------------------------
// Per-row: radix-select kk-th largest |score|, local+sparse mask, softmax.
// ---------------------------------------------------------------------------
__global__ __launch_bounds__(256)
void mask_softmax_kernel(float* __restrict__ scores)
{
    int i  = blockIdx.x;
    int hd = blockIdx.y;
    float* row = scores + ((size_t)hd * S_LEN + i) * S_LEN;

    __shared__ float srow[S_LEN];
    __shared__ int   hist[256];
    __shared__ int   sh_sel[2];
    __shared__ float red[256];

    int tid = threadIdx.x;
    for (int j = tid; j < S_LEN; j += 256) srow[j] = row[j];
    __syncthreads();

    unsigned prefix = 0;
    int kneed = KK;
#pragma unroll
    for (int byte = 3; byte >= 0; --byte) {
        hist[tid] = 0;
        __syncthreads();
        unsigned pm = (byte == 3) ? 0u : (0xFFFFFFFFu << (8 * (byte + 1)));
        for (int j = tid; j < S_LEN; j += 256) {
            unsigned bits = __float_as_uint(fabsf(srow[j]));
            if ((bits & pm) == prefix)
                atomicAdd(&hist[(bits >> (8 * byte)) & 255], 1);
        }
        __syncthreads();
        if (tid == 0) {
            int cacc = 0, sel = 0, kn = kneed;
            for (int b = 255; b >= 0; --b) {
                cacc += hist[b];
                if (cacc >= kn) { sel = b; kn -= (cacc - hist[b]); break; }
            }
            sh_sel[0] = sel; sh_sel[1] = kn;
        }
        __syncthreads();
        prefix |= ((unsigned)sh_sel[0]) << (8 * byte);
        kneed = sh_sel[1];
        __syncthreads();
    }
    unsigned T = prefix;

    int jmax = i + WINDOW;
    float m = -INFINITY;
    for (int j = tid; j < S_LEN; j += 256) {
        float s = srow[j];
        bool keep = (j <= jmax) && (__float_as_uint(fabsf(s)) >= T);
        float sv = keep ? s : -INFINITY;
        srow[j] = sv;
        m = fmaxf(m, sv);
    }
    red[tid] = m; __syncthreads();
#pragma unroll
    for (int st = 128; st; st >>= 1) {
        if (tid < st) red[tid] = fmaxf(red[tid], red[tid + st]);
        __syncthreads();
    }
    m = red[0];
    __syncthreads();

    float z = 0.f;
    for (int j = tid; j < S_LEN; j += 256) {
        float s = srow[j];
        float e = (s == -INFINITY) ? 0.f : __expf(s - m);
        srow[j] = e;
        z += e;
    }
    red[tid] = z; __syncthreads();
#pragma unroll
    for (int st = 128; st; st >>= 1) {
        if (tid < st) red[tid] += red[tid + st];
        __syncthreads();
    }
    z = red[0];
    float inv = (z > 0.f) ? 1.f / z : 0.f;
    for (int j = tid; j < S_LEN; j += 256) row[j] = srow[j] * inv;
}

// ---------------------------------------------------------------------------
// Launch
// ---------------------------------------------------------------------------
extern "C" void kernel_launch(void* const* d_in, const int* in_sizes, int n_in,
                              void* d_out, int out_size)
{
    const float* x      = (const float*)d_in[0];
    const float* Amat   = (const float*)d_in[1];
    const float* Bm     = (const float*)d_in[2];
    const float* Cm     = (const float*)d_in[3];
    const float* log_dt = (const float*)d_in[4];
    const float* Wg = (const float*)d_in[5];  const float* bg = (const float*)d_in[6];
    const float* Wq = (const float*)d_in[7];  const float* bq = (const float*)d_in[8];
    const float* Wk = (const float*)d_in[9];  const float* bk = (const float*)d_in[10];
    const float* Wv = (const float*)d_in[11]; const float* bv = (const float*)d_in[12];
    const float* Wd = (const float*)d_in[13]; const float* bd = (const float*)d_in[14];
    float* out = (float*)d_out;

    float *gate, *H, *Q, *K, *V, *ctx, *scores;
    cudaGetSymbolAddress((void**)&gate,   g_gate);
    cudaGetSymbolAddress((void**)&H,      g_H);
    cudaGetSymbolAddress((void**)&Q,      g_Q);
    cudaGetSymbolAddress((void**)&K,      g_K);
    cudaGetSymbolAddress((void**)&V,      g_V);
    cudaGetSymbolAddress((void**)&ctx,    g_ctx);
    cudaGetSymbolAddress((void**)&scores, g_scores);

    dim3 blk(256);

    // 1) gate = sigmoid(X Wg^T + bg)
    {
        dim3 grid(D_DIM / 64, S_LEN / 128, 1);
        gemm_tc<true, 2><<<grid, blk>>>(x, Wg, bg, gate,
            S_LEN, D_DIM, D_DIM, D_DIM, D_DIM, D_DIM, 0, 0, 0, 1.f, 0);
    }
    // 2) SSM scan -> H = x + y
    ssm_kernel<<<D_DIM / 8, 128>>>(x, gate, Amat, Bm, Cm, log_dt, H);

    // 3) Q, K, V projections from H
    {
        dim3 grid(D_DIM / 64, S_LEN / 128, 1);
        gemm_tc<true, 1><<<grid, blk>>>(H, Wq, bq, Q,
            S_LEN, D_DIM, D_DIM, D_DIM, D_DIM, D_DIM, 0, 0, 0, 1.f, 0);
        gemm_tc<true, 1><<<grid, blk>>>(H, Wk, bk, K,
            S_LEN, D_DIM, D_DIM, D_DIM, D_DIM, D_DIM, 0, 0, 0, 1.f, 0);
        gemm_tc<true, 1><<<grid, blk>>>(H, Wv, bv, V,
            S_LEN, D_DIM, D_DIM, D_DIM, D_DIM, D_DIM, 0, 0, 0, 1.f, 0);
    }
    // 4) scores[h] = Q_h K_h^T / 8
    {
        dim3 grid(S_LEN / 64, S_LEN / 128, N_HEADS);
        gemm_tc<true, 0><<<grid, blk>>>(Q, K, nullptr, scores,
            S_LEN, S_LEN, DH, D_DIM, D_DIM, S_LEN,
            DH, DH, (long)S_LEN * S_LEN, 0.125f, 0);
    }
    // 5) per-row top-k select + masks + softmax (in place)
    {
        dim3 grid(S_LEN, N_HEADS);
        mask_softmax_kernel<<<grid, blk>>>(scores);
    }
    // 6) ctx[h] = P_h V_h   (banded: P zero for j > i+WINDOW)
    {
        dim3 grid(DH / 64, S_LEN / 128, N_HEADS);
        gemm_tc<false, 0><<<grid, blk>>>(scores, V, nullptr, ctx,
            S_LEN, DH, S_LEN, S_LEN, D_DIM, D_DIM,
            (long)S_LEN * S_LEN, DH, DH, 1.f, 128 + WINDOW);
    }
    // 7) out = ctx Wd^T + bd
    {
        dim3 grid(D_DIM / 64, S_LEN / 128, 1);
        gemm_tc<true, 1><<<grid, blk>>>(ctx, Wd, bd, out,
            S_LEN, D_DIM, D_DIM, D_DIM, D_DIM, D_DIM, 0, 0, 0, 1.f, 0);
    }
}

// round 5
// speedup vs baseline: 1.4886x; 1.0913x over previous
#include <cuda_runtime.h>
#include <cuda_bf16.h>
#include <math.h>
#include <stdint.h>

// Problem constants
#define S_LEN 2048
#define D_DIM 768
#define N_STATE 16
#define N_HEADS 12
#define DH 64
#define WINDOW 128
#define KK 1843            // int((1-0.1)*2048)
#define SPIKE 0.1f
#define FULLM 0xffffffffu

// ---------------------------------------------------------------------------
// Scratch (device globals; no dynamic allocation allowed)
// ---------------------------------------------------------------------------
__device__ float g_gate[S_LEN * D_DIM];
__device__ float g_H[S_LEN * D_DIM];
__device__ float g_Q[S_LEN * D_DIM];
__device__ float g_K[S_LEN * D_DIM];
__device__ float g_V[S_LEN * D_DIM];
__device__ float g_ctx[S_LEN * D_DIM];
__device__ float g_scores[(size_t)N_HEADS * S_LEN * S_LEN];   // 192 MB

// ---------------------------------------------------------------------------
// Split-TF32 helpers (4-MMA emulation of fp32 GEMM on tensor cores)
// ---------------------------------------------------------------------------
__device__ __forceinline__ void split_tf32(float a, uint32_t& hi, uint32_t& lo) {
    asm("cvt.rna.tf32.f32 %0, %1;" : "=r"(hi) : "f"(a));
    float r = a - __uint_as_float(hi);
    asm("cvt.rna.tf32.f32 %0, %1;" : "=r"(lo) : "f"(r));
}

__device__ __forceinline__ void mma8(float c[4], const uint32_t a[4], const uint32_t b[2]) {
    asm("mma.sync.aligned.m16n8k8.row.col.f32.tf32.tf32.f32 "
        "{%0,%1,%2,%3},{%4,%5,%6,%7},{%8,%9},{%0,%1,%2,%3};"
        : "+f"(c[0]), "+f"(c[1]), "+f"(c[2]), "+f"(c[3])
        : "r"(a[0]), "r"(a[1]), "r"(a[2]), "r"(a[3]), "r"(b[0]), "r"(b[1]));
}

// ---------------------------------------------------------------------------
// Tensor-core GEMM (split tf32, fp32-grade accuracy):
//   BT=true : C[m,n] = alpha * sum_k A[m,k]*B[n,k]  (+bias) (+sigmoid)
//   BT=false: C[m,n] = alpha * sum_k A[m,k]*B[k,n]
// EPI: 0 none, 1 +bias, 2 sigmoid(v+bias), 3 atomicAdd (split-K)
// band>0: limit k-range to row0+band (banded A, e.g. windowed P in PV).
// SPLITK: blockIdx.z = batch*SPLITK + part; each part does a k-chunk.
// ---------------------------------------------------------------------------
template<bool BT, int EPI, int SPLITK>
__global__ __launch_bounds__(256)
void gemm_tc(const float* __restrict__ A, const float* __restrict__ B,
             const float* __restrict__ bias, float* __restrict__ C,
             int M, int N, int K, int lda, int ldb, int ldc,
             long Astride, long Bstride, long Cstride, float alpha, int band)
{
    int bz   = blockIdx.z / SPLITK;
    int part = blockIdx.z % SPLITK;
    A += (long)bz * Astride;
    B += (long)bz * Bstride;
    C += (long)bz * Cstride;

    const int BM = 128, BN = 64, BK = 32, LD = BK + 4;   // padded stride 36
    __shared__ float As[BM * LD];   // 18 KB
    __shared__ float Bs[BN * LD];   // 9 KB

    int tid  = threadIdx.x;
    int lane = tid & 31;
    int wid  = tid >> 5;
    int wm   = wid >> 1;            // 0..3
    int wn   = wid & 1;             // 0..1
    int g    = lane >> 2;           // groupID 0..7
    int tg   = lane & 3;            // thread-in-group

    int row0 = blockIdx.y * BM;
    int col0 = blockIdx.x * BN;

    float c[2][4][4];
#pragma unroll
    for (int mi = 0; mi < 2; mi++)
#pragma unroll
        for (int ni = 0; ni < 4; ni++)
#pragma unroll
            for (int r = 0; r < 4; r++) c[mi][ni][r] = 0.f;

    int Keff  = band > 0 ? min(K, row0 + band) : K;
    int tiles = Keff / BK;
    int tA = (tiles * part) / SPLITK;
    int tB = (tiles * (part + 1)) / SPLITK;

    for (int k0 = tA * BK; k0 < tB * BK; k0 += BK) {
        // ---- load A tile (128 x 32), vectorized ----
#pragma unroll
        for (int i = 0; i < 4; i++) {
            int idx = tid + i * 256;           // 1024 float4s
            int m = idx >> 3, kc = (idx & 7) << 2;
            float4 v = *(const float4*)&A[(long)(row0 + m) * lda + (k0 + kc)];
            *(float4*)&As[m * LD + kc] = v;
        }
        // ---- load B tile into Bs[n][k] ----
        if (BT) {
#pragma unroll
            for (int i = 0; i < 2; i++) {
                int idx = tid + i * 256;       // 512 float4s
                int n = idx >> 3, kc = (idx & 7) << 2;
                float4 v = *(const float4*)&B[(long)(col0 + n) * ldb + (k0 + kc)];
                *(float4*)&Bs[n * LD + kc] = v;
            }
        } else {
#pragma unroll
            for (int i = 0; i < 2; i++) {
                int idx = tid + i * 256;       // 512 float4s over [32k x 64n]
                int kk = idx >> 4, nc = (idx & 15) << 2;
                float4 v = *(const float4*)&B[(long)(k0 + kk) * ldb + (col0 + nc)];
                Bs[(nc + 0) * LD + kk] = v.x;
                Bs[(nc + 1) * LD + kk] = v.y;
                Bs[(nc + 2) * LD + kk] = v.z;
                Bs[(nc + 3) * LD + kk] = v.w;
            }
        }
        __syncthreads();

#pragma unroll
        for (int ks = 0; ks < BK; ks += 8) {
            uint32_t ah[2][4], al[2][4];
#pragma unroll
            for (int mi = 0; mi < 2; mi++) {
                int mb = wm * 32 + mi * 16;
                float f0 = As[(mb + g)     * LD + ks + tg];
                float f1 = As[(mb + g + 8) * LD + ks + tg];
                float f2 = As[(mb + g)     * LD + ks + tg + 4];
                float f3 = As[(mb + g + 8) * LD + ks + tg + 4];
                split_tf32(f0, ah[mi][0], al[mi][0]);
                split_tf32(f1, ah[mi][1], al[mi][1]);
                split_tf32(f2, ah[mi][2], al[mi][2]);
                split_tf32(f3, ah[mi][3], al[mi][3]);
            }
            uint32_t bh[4][2], bl[4][2];
#pragma unroll
            for (int ni = 0; ni < 4; ni++) {
                int nb = wn * 32 + ni * 8 + g;
                float f0 = Bs[nb * LD + ks + tg];
                float f1 = Bs[nb * LD + ks + tg + 4];
                split_tf32(f0, bh[ni][0], bl[ni][0]);
                split_tf32(f1, bh[ni][1], bl[ni][1]);
            }
            // 4-MMA split accumulate (full fp32-grade precision)
#pragma unroll
            for (int mi = 0; mi < 2; mi++)
#pragma unroll
                for (int ni = 0; ni < 4; ni++) {
                    mma8(c[mi][ni], ah[mi], bh[ni]);
                    mma8(c[mi][ni], ah[mi], bl[ni]);
                    mma8(c[mi][ni], al[mi], bh[ni]);
                    mma8(c[mi][ni], al[mi], bl[ni]);
                }
        }
        __syncthreads();
    }

    // ---- epilogue ----
#pragma unroll
    for (int mi = 0; mi < 2; mi++) {
#pragma unroll
        for (int ni = 0; ni < 4; ni++) {
            int row = row0 + wm * 32 + mi * 16 + g;
            int col = col0 + wn * 32 + ni * 8 + 2 * tg;
            float v0 = c[mi][ni][0] * alpha;
            float v1 = c[mi][ni][1] * alpha;
            float v2 = c[mi][ni][2] * alpha;
            float v3 = c[mi][ni][3] * alpha;
            if (EPI == 3) {
                atomicAdd(&C[(long)row * ldc + col],           v0);
                atomicAdd(&C[(long)row * ldc + col + 1],       v1);
                atomicAdd(&C[(long)(row + 8) * ldc + col],     v2);
                atomicAdd(&C[(long)(row + 8) * ldc + col + 1], v3);
            } else {
                if (EPI >= 1) {
                    float b0 = bias[col], b1 = bias[col + 1];
                    v0 += b0; v1 += b1; v2 += b0; v3 += b1;
                }
                if (EPI == 2) {
                    v0 = 1.f / (1.f + expf(-v0));
                    v1 = 1.f / (1.f + expf(-v1));
                    v2 = 1.f / (1.f + expf(-v2));
                    v3 = 1.f / (1.f + expf(-v3));
                }
                *(float2*)&C[(long)row * ldc + col]       = make_float2(v0, v1);
                *(float2*)&C[(long)(row + 8) * ldc + col] = make_float2(v2, v3);
            }
        }
    }
}

// ---------------------------------------------------------------------------
// SSM sequential scan. 16 lanes per channel (lane = state index n).
// ILP: 4 independent FMA chains, prefetch of next-step x/gate, branchless spike.
// ---------------------------------------------------------------------------
__global__ __launch_bounds__(128)
void ssm_kernel(const float* __restrict__ x, const float* __restrict__ gate,
                const float* __restrict__ Amat, const float* __restrict__ Bm,
                const float* __restrict__ Cm, const float* __restrict__ log_dt,
                float* __restrict__ Hout)
{
    int lane = threadIdx.x & 15;                       // state index n
    int d = blockIdx.x * (blockDim.x >> 4) + (threadIdx.x >> 4);
    if (d >= D_DIM) return;

    float Arow[N_STATE];
#pragma unroll
    for (int m = 0; m < N_STATE; m++) Arow[m] = Amat[lane * N_STATE + m];
    float Bn  = Bm[lane * D_DIM + d];
    float Cn  = Cm[d * N_STATE + lane];
    float dtd = fminf(fmaxf(expf(log_dt[d]), 1e-3f), 1e-1f);

    float h  = 0.f;
    float xv = __ldg(&x[d]);
    float gv = __ldg(&gate[d]);

    for (int t = 0; t < S_LEN; t++) {
        // prefetch next step's inputs (off critical path)
        float xn = 0.f, gn = 0.f;
        if (t + 1 < S_LEN) {
            xn = __ldg(&x[(t + 1) * D_DIM + d]);
            gn = __ldg(&gate[(t + 1) * D_DIM + d]);
        }
        float p0 = 0.f, p1 = 0.f, p2 = 0.f, p3 = 0.f;
#pragma unroll
        for (int m = 0; m < 4; m++) {
            p0 = fmaf(Arow[m],      __shfl_sync(FULLM, h, m,      16), p0);
            p1 = fmaf(Arow[m + 4],  __shfl_sync(FULLM, h, m + 4,  16), p1);
            p2 = fmaf(Arow[m + 8],  __shfl_sync(FULLM, h, m + 8,  16), p2);
            p3 = fmaf(Arow[m + 12], __shfl_sync(FULLM, h, m + 12, 16), p3);
        }
        float acc = (p0 + p1) + (p2 + p3);
        float sc  = (acc + xv * Bn) * dtd;
        float gm  = (fabsf(sc) > SPIKE) ? gv : 0.f;
        h = fmaf(sc, gm, h);

        float pr = h * Cn;
#pragma unroll
        for (int off = 8; off; off >>= 1)
            pr += __shfl_xor_sync(FULLM, pr, off, 16);
        if (lane == 0) Hout[t * D_DIM + d] = xv + pr;

        xv = xn; gv = gn;
    }
}

// ---------------------------------------------------------------------------
// Per-row: radix-select kk-th largest |score|, local+sparse mask, softmax.
// Row lives in registers (8 floats/thread). Per-warp histograms + warp-0
// shuffle suffix-scan (no serial bin walk, no smem row buffer).
// ---------------------------------------------------------------------------
__global__ __launch_bounds__(256)
void mask_softmax_kernel(float* __restrict__ scores)
{
    int i  = blockIdx.x;
    int hd = blockIdx.y;
    float* row = scores + ((size_t)hd * S_LEN + i) * S_LEN;

    __shared__ int   hist[8][256];
    __shared__ int   red[256];
    __shared__ int   sh_sel[2];
    __shared__ float fred[8];

    int tid = threadIdx.x, lane = tid & 31, wid = tid >> 5;

    float r[8]; unsigned u[8];
    {
        float4 v0 = *(const float4*)&row[tid * 8];
        float4 v1 = *(const float4*)&row[tid * 8 + 4];
        r[0] = v0.x; r[1] = v0.y; r[2] = v0.z; r[3] = v0.w;
        r[4] = v1.x; r[5] = v1.y; r[6] = v1.z; r[7] = v1.w;
    }
#pragma unroll
    for (int e = 0; e < 8; e++) u[e] = __float_as_uint(fabsf(r[e]));

    unsigned prefix = 0;
    int kneed = KK;
#pragma unroll
    for (int byte = 3; byte >= 0; --byte) {
        for (int b = lane; b < 256; b += 32) hist[wid][b] = 0;
        __syncthreads();
        unsigned pm = (byte == 3) ? 0u : (0xFFFFFFFFu << (8 * (byte + 1)));
#pragma unroll
        for (int e = 0; e < 8; e++)
            if ((u[e] & pm) == prefix)
                atomicAdd(&hist[wid][(u[e] >> (8 * byte)) & 255], 1);
        __syncthreads();
        int cnt = 0;
#pragma unroll
        for (int w = 0; w < 8; w++) cnt += hist[w][tid];
        red[tid] = cnt;
        __syncthreads();
        if (wid == 0) {
            // lane l covers bins 255-(8l) .. 255-(8l+7), descending
            int v[8], cum[8], s = 0;
#pragma unroll
            for (int e = 0; e < 8; e++) {
                v[e] = red[255 - (lane * 8 + e)];
                s += v[e];
                cum[e] = s;
            }
            int incl = s;
#pragma unroll
            for (int off = 1; off < 32; off <<= 1) {
                int t2 = __shfl_up_sync(FULLM, incl, off);
                if (lane >= off) incl += t2;
            }
            int excl = incl - s;
            bool has = (excl + cum[7]) >= kneed && excl < kneed;
            unsigned bal = __ballot_sync(FULLM, has);
            int fl = __ffs(bal) - 1;
            if (lane == fl) {
                int e = 0;
                while (excl + cum[e] < kneed) e++;
                sh_sel[0] = 255 - (lane * 8 + e);
                sh_sel[1] = kneed - (excl + cum[e] - v[e]);
            }
        }
        __syncthreads();
        prefix |= ((unsigned)sh_sel[0]) << (8 * byte);
        kneed = sh_sel[1];
        __syncthreads();
    }
    unsigned T = prefix;

    // ---- masks + max (all in registers) ----
    int jmax = i + WINDOW;
    float m = -INFINITY;
    float sv[8];
#pragma unroll
    for (int e = 0; e < 8; e++) {
        int j = tid * 8 + e;
        bool keep = (j <= jmax) && (u[e] >= T);
        sv[e] = keep ? r[e] : -INFINITY;
        m = fmaxf(m, sv[e]);
    }
#pragma unroll
    for (int off = 16; off; off >>= 1)
        m = fmaxf(m, __shfl_xor_sync(FULLM, m, off));
    if (lane == 0) fred[wid] = m;
    __syncthreads();
    float mm = -INFINITY;
#pragma unroll
    for (int w = 0; w < 8; w++) mm = fmaxf(mm, fred[w]);
    __syncthreads();

    // ---- exp + sum ----
    float z = 0.f;
    float ex[8];
#pragma unroll
    for (int e = 0; e < 8; e++) {
        ex[e] = (sv[e] == -INFINITY) ? 0.f : __expf(sv[e] - mm);
        z += ex[e];
    }
#pragma unroll
    for (int off = 16; off; off >>= 1)
        z += __shfl_xor_sync(FULLM, z, off);
    if (lane == 0) fred[wid] = z;
    __syncthreads();
    float zz = 0.f;
#pragma unroll
    for (int w = 0; w < 8; w++) zz += fred[w];
    float inv = (zz > 0.f) ? 1.f / zz : 0.f;

    float4 o0 = make_float4(ex[0] * inv, ex[1] * inv, ex[2] * inv, ex[3] * inv);
    float4 o1 = make_float4(ex[4] * inv, ex[5] * inv, ex[6] * inv, ex[7] * inv);
    *(float4*)&row[tid * 8]     = o0;
    *(float4*)&row[tid * 8 + 4] = o1;
}

// ---------------------------------------------------------------------------
// Launch
// ---------------------------------------------------------------------------
extern "C" void kernel_launch(void* const* d_in, const int* in_sizes, int n_in,
                              void* d_out, int out_size)
{
    const float* x      = (const float*)d_in[0];
    const float* Amat   = (const float*)d_in[1];
    const float* Bm     = (const float*)d_in[2];
    const float* Cm     = (const float*)d_in[3];
    const float* log_dt = (const float*)d_in[4];
    const float* Wg = (const float*)d_in[5];  const float* bg = (const float*)d_in[6];
    const float* Wq = (const float*)d_in[7];  const float* bq = (const float*)d_in[8];
    const float* Wk = (const float*)d_in[9];  const float* bk = (const float*)d_in[10];
    const float* Wv = (const float*)d_in[11]; const float* bv = (const float*)d_in[12];
    const float* Wd = (const float*)d_in[13]; const float* bd = (const float*)d_in[14];
    float* out = (float*)d_out;

    float *gate, *H, *Q, *K, *V, *ctx, *scores;
    cudaGetSymbolAddress((void**)&gate,   g_gate);
    cudaGetSymbolAddress((void**)&H,      g_H);
    cudaGetSymbolAddress((void**)&Q,      g_Q);
    cudaGetSymbolAddress((void**)&K,      g_K);
    cudaGetSymbolAddress((void**)&V,      g_V);
    cudaGetSymbolAddress((void**)&ctx,    g_ctx);
    cudaGetSymbolAddress((void**)&scores, g_scores);

    dim3 blk(256);

    // 1) gate = sigmoid(X Wg^T + bg)
    {
        dim3 grid(D_DIM / 64, S_LEN / 128, 1);
        gemm_tc<true, 2, 1><<<grid, blk>>>(x, Wg, bg, gate,
            S_LEN, D_DIM, D_DIM, D_DIM, D_DIM, D_DIM, 0, 0, 0, 1.f, 0);
    }
    // 2) SSM scan -> H = x + y
    ssm_kernel<<<D_DIM / 8, 128>>>(x, gate, Amat, Bm, Cm, log_dt, H);

    // 3) Q, K, V projections from H
    {
        dim3 grid(D_DIM / 64, S_LEN / 128, 1);
        gemm_tc<true, 1, 1><<<grid, blk>>>(H, Wq, bq, Q,
            S_LEN, D_DIM, D_DIM, D_DIM, D_DIM, D_DIM, 0, 0, 0, 1.f, 0);
        gemm_tc<true, 1, 1><<<grid, blk>>>(H, Wk, bk, K,
            S_LEN, D_DIM, D_DIM, D_DIM, D_DIM, D_DIM, 0, 0, 0, 1.f, 0);
        gemm_tc<true, 1, 1><<<grid, blk>>>(H, Wv, bv, V,
            S_LEN, D_DIM, D_DIM, D_DIM, D_DIM, D_DIM, 0, 0, 0, 1.f, 0);
    }
    // 4) scores[h] = Q_h K_h^T / 8
    {
        dim3 grid(S_LEN / 64, S_LEN / 128, N_HEADS);
        gemm_tc<true, 0, 1><<<grid, blk>>>(Q, K, nullptr, scores,
            S_LEN, S_LEN, DH, D_DIM, D_DIM, S_LEN,
            DH, DH, (long)S_LEN * S_LEN, 0.125f, 0);
    }
    // 5) per-row top-k select + masks + softmax (in place)
    {
        dim3 grid(S_LEN, N_HEADS);
        mask_softmax_kernel<<<grid, blk>>>(scores);
    }
    // 6) ctx[h] = P_h V_h   (banded, split-K=2, deterministic atomic adds)
    {
        cudaMemsetAsync(ctx, 0, (size_t)S_LEN * D_DIM * sizeof(float));
        dim3 grid(DH / 64, S_LEN / 128, N_HEADS * 2);
        gemm_tc<false, 3, 2><<<grid, blk>>>(scores, V, nullptr, ctx,
            S_LEN, DH, S_LEN, S_LEN, D_DIM, D_DIM,
            (long)S_LEN * S_LEN, DH, DH, 1.f, 128 + WINDOW);
    }
    // 7) out = ctx Wd^T + bd
    {
        dim3 grid(D_DIM / 64, S_LEN / 128, 1);
        gemm_tc<true, 1, 1><<<grid, blk>>>(ctx, Wd, bd, out,
            S_LEN, D_DIM, D_DIM, D_DIM, D_DIM, D_DIM, 0, 0, 0, 1.f, 0);
    }
}

// round 6
// speedup vs baseline: 1.7562x; 1.1798x over previous
#include <cuda_runtime.h>
#include <cuda_bf16.h>
#include <math.h>
#include <stdint.h>

// Problem constants
#define S_LEN 2048
#define D_DIM 768
#define N_STATE 16
#define N_HEADS 12
#define DH 64
#define WINDOW 128
#define KK 1843            // int((1-0.1)*2048)
#define SPIKE 0.1f
#define FULLM 0xffffffffu

// ---------------------------------------------------------------------------
// Scratch (device globals; no dynamic allocation allowed)
// ---------------------------------------------------------------------------
__device__ float g_gate[S_LEN * D_DIM];
__device__ float g_H[S_LEN * D_DIM];
__device__ float g_Q[S_LEN * D_DIM];
__device__ float g_K[S_LEN * D_DIM];
__device__ float g_V[S_LEN * D_DIM];
__device__ float g_ctx[S_LEN * D_DIM];
__device__ float g_scores[(size_t)N_HEADS * S_LEN * S_LEN];   // 192 MB

// ---------------------------------------------------------------------------
// Split-TF32 helpers (3-MMA emulation of fp32 GEMM on tensor cores)
// ---------------------------------------------------------------------------
__device__ __forceinline__ void split_tf32(float a, uint32_t& hi, uint32_t& lo) {
    asm("cvt.rna.tf32.f32 %0, %1;" : "=r"(hi) : "f"(a));
    float r = a - __uint_as_float(hi);
    asm("cvt.rna.tf32.f32 %0, %1;" : "=r"(lo) : "f"(r));
}

__device__ __forceinline__ void mma8(float c[4], const uint32_t a[4], const uint32_t b[2]) {
    asm("mma.sync.aligned.m16n8k8.row.col.f32.tf32.tf32.f32 "
        "{%0,%1,%2,%3},{%4,%5,%6,%7},{%8,%9},{%0,%1,%2,%3};"
        : "+f"(c[0]), "+f"(c[1]), "+f"(c[2]), "+f"(c[3])
        : "r"(a[0]), "r"(a[1]), "r"(a[2]), "r"(a[3]), "r"(b[0]), "r"(b[1]));
}

#define CPA16(dst, src) asm volatile("cp.async.ca.shared.global [%0], [%1], 16;" :: "r"(dst), "l"(src))
#define CPCOMMIT()      asm volatile("cp.async.commit_group;" ::: "memory")
#define CPWAIT1()       asm volatile("cp.async.wait_group 1;" ::: "memory")
#define CPWAIT0()       asm volatile("cp.async.wait_group 0;" ::: "memory")

// ---------------------------------------------------------------------------
// Tensor-core GEMM (split tf32, 3-MMA):
//   BT=true : C[m,n] = alpha * sum_k A[m,k]*B[n,k]  (+bias) (+sigmoid)
//   BT=false: C[m,n] = alpha * sum_k A[m,k]*B[k,n]
// EPI: 0 none, 1 +bias, 2 sigmoid(v+bias), 3 atomicAdd (split-K)
// Tiles BM=BN=64, BK=32; 256 thr, 8 warps (2m x 4n), warp tile 32x16.
// 2-stage cp.async pipeline. Multi-matrix fusion: B/bias/C selected by
// blockIdx.x / nper (for fused QKV).
// band>0: limit k-range to row0+band. SPLITK parts via blockIdx.z.
// ---------------------------------------------------------------------------
template<bool BT, int EPI, int SPLITK>
__global__ __launch_bounds__(256)
void gemm_tc(const float* __restrict__ A,
             const float* __restrict__ B0, const float* __restrict__ B1,
             const float* __restrict__ B2,
             const float* __restrict__ bi0, const float* __restrict__ bi1,
             const float* __restrict__ bi2,
             float* __restrict__ C0, float* __restrict__ C1, float* __restrict__ C2,
             int K, int lda, int ldb, int ldc,
             long Astride, long Bstride, long Cstride,
             float alpha, int band, int nper)
{
    int bz   = blockIdx.z / SPLITK;
    int part = blockIdx.z % SPLITK;
    int sel  = blockIdx.x / nper;
    int xb   = blockIdx.x % nper;

    const float* B    = (sel == 0) ? B0  : (sel == 1) ? B1  : B2;
    const float* bias = (sel == 0) ? bi0 : (sel == 1) ? bi1 : bi2;
    float*       C    = (sel == 0) ? C0  : (sel == 1) ? C1  : C2;

    A += (long)bz * Astride;
    B += (long)bz * Bstride;
    C += (long)bz * Cstride;

    const int BK = 32;
    // As rows stride 36; Bs: BT -> [n][36], !BT -> [k][72]; both 2304 floats
    __shared__ float As[2][64 * 36];
    __shared__ float Bs[2][2304];

    int tid  = threadIdx.x;
    int lane = tid & 31;
    int wid  = tid >> 5;
    int wm   = wid >> 2;            // 0..1
    int wn   = wid & 3;             // 0..3
    int g    = lane >> 2;           // 0..7
    int tg   = lane & 3;            // 0..3

    int row0 = blockIdx.y * 64;
    int col0 = xb * 64;

    unsigned asb = (unsigned)__cvta_generic_to_shared(&As[0][0]);
    unsigned bsb = (unsigned)__cvta_generic_to_shared(&Bs[0][0]);

    float c[2][2][4];
#pragma unroll
    for (int mi = 0; mi < 2; mi++)
#pragma unroll
        for (int ni = 0; ni < 2; ni++)
#pragma unroll
            for (int r = 0; r < 4; r++) c[mi][ni][r] = 0.f;

    int Keff  = band > 0 ? min(K, row0 + band) : K;
    int tiles = Keff / BK;
    int tA = (tiles * part) / SPLITK;
    int tB = (tiles * (part + 1)) / SPLITK;
    int T  = tB - tA;

    auto load_tile = [&](int tk, int st) {
        int k0 = tk * BK;
        unsigned asd = asb + st * (64 * 36 * 4);
        unsigned bsd = bsb + st * (2304 * 4);
#pragma unroll
        for (int i = 0; i < 2; i++) {
            int idx = tid + i * 256;
            int m = idx >> 3, kc = (idx & 7) << 2;
            CPA16(asd + (m * 36 + kc) * 4, &A[(long)(row0 + m) * lda + k0 + kc]);
        }
        if (BT) {
#pragma unroll
            for (int i = 0; i < 2; i++) {
                int idx = tid + i * 256;
                int n = idx >> 3, kc = (idx & 7) << 2;
                CPA16(bsd + (n * 36 + kc) * 4, &B[(long)(col0 + n) * ldb + k0 + kc]);
            }
        } else {
#pragma unroll
            for (int i = 0; i < 2; i++) {
                int idx = tid + i * 256;
                int kk = idx >> 4, nc = (idx & 15) << 2;
                CPA16(bsd + (kk * 72 + nc) * 4, &B[(long)(k0 + kk) * ldb + col0 + nc]);
            }
        }
        CPCOMMIT();
    };

    if (T > 0) load_tile(tA, 0);

    for (int t = 0; t < T; t++) {
        if (t + 1 < T) { load_tile(tA + t + 1, (t + 1) & 1); CPWAIT1(); }
        else           { CPWAIT0(); }
        __syncthreads();

        const float* as = As[t & 1];
        const float* bs = Bs[t & 1];
#pragma unroll
        for (int ks = 0; ks < BK; ks += 8) {
            uint32_t ah[2][4], al[2][4];
#pragma unroll
            for (int mi = 0; mi < 2; mi++) {
                int mb = wm * 32 + mi * 16;
                float f0 = as[(mb + g)     * 36 + ks + tg];
                float f1 = as[(mb + g + 8) * 36 + ks + tg];
                float f2 = as[(mb + g)     * 36 + ks + tg + 4];
                float f3 = as[(mb + g + 8) * 36 + ks + tg + 4];
                split_tf32(f0, ah[mi][0], al[mi][0]);
                split_tf32(f1, ah[mi][1], al[mi][1]);
                split_tf32(f2, ah[mi][2], al[mi][2]);
                split_tf32(f3, ah[mi][3], al[mi][3]);
            }
            uint32_t bh[2][2], bl[2][2];
#pragma unroll
            for (int ni = 0; ni < 2; ni++) {
                int nb = wn * 16 + ni * 8 + g;
                float f0 = BT ? bs[nb * 36 + ks + tg]     : bs[(ks + tg)     * 72 + nb];
                float f1 = BT ? bs[nb * 36 + ks + tg + 4] : bs[(ks + tg + 4) * 72 + nb];
                split_tf32(f0, bh[ni][0], bl[ni][0]);
                split_tf32(f1, bh[ni][1], bl[ni][1]);
            }
#pragma unroll
            for (int mi = 0; mi < 2; mi++)
#pragma unroll
                for (int ni = 0; ni < 2; ni++) {
                    mma8(c[mi][ni], ah[mi], bh[ni]);
                    mma8(c[mi][ni], ah[mi], bl[ni]);
                    mma8(c[mi][ni], al[mi], bh[ni]);
                }
        }
        __syncthreads();
    }

    // ---- epilogue ----
#pragma unroll
    for (int mi = 0; mi < 2; mi++) {
#pragma unroll
        for (int ni = 0; ni < 2; ni++) {
            int row = row0 + wm * 32 + mi * 16 + g;
            int col = col0 + wn * 16 + ni * 8 + 2 * tg;
            float v0 = c[mi][ni][0] * alpha;
            float v1 = c[mi][ni][1] * alpha;
            float v2 = c[mi][ni][2] * alpha;
            float v3 = c[mi][ni][3] * alpha;
            if (EPI == 3) {
                atomicAdd(&C[(long)row * ldc + col],           v0);
                atomicAdd(&C[(long)row * ldc + col + 1],       v1);
                atomicAdd(&C[(long)(row + 8) * ldc + col],     v2);
                atomicAdd(&C[(long)(row + 8) * ldc + col + 1], v3);
            } else {
                if (EPI >= 1) {
                    float b0 = bias[col], b1 = bias[col + 1];
                    v0 += b0; v1 += b1; v2 += b0; v3 += b1;
                }
                if (EPI == 2) {
                    v0 = 1.f / (1.f + expf(-v0));
                    v1 = 1.f / (1.f + expf(-v1));
                    v2 = 1.f / (1.f + expf(-v2));
                    v3 = 1.f / (1.f + expf(-v3));
                }
                *(float2*)&C[(long)row * ldc + col]       = make_float2(v0, v1);
                *(float2*)&C[(long)(row + 8) * ldc + col] = make_float2(v2, v3);
            }
        }
    }
}

// ---------------------------------------------------------------------------
// SSM sequential scan. 16 lanes per channel (lane = state index n).
// ---------------------------------------------------------------------------
__global__ __launch_bounds__(128)
void ssm_kernel(const float* __restrict__ x, const float* __restrict__ gate,
                const float* __restrict__ Amat, const float* __restrict__ Bm,
                const float* __restrict__ Cm, const float* __restrict__ log_dt,
                float* __restrict__ Hout)
{
    int lane = threadIdx.x & 15;
    int d = blockIdx.x * (blockDim.x >> 4) + (threadIdx.x >> 4);
    if (d >= D_DIM) return;

    float Arow[N_STATE];
#pragma unroll
    for (int m = 0; m < N_STATE; m++) Arow[m] = Amat[lane * N_STATE + m];
    float Bn  = Bm[lane * D_DIM + d];
    float Cn  = Cm[d * N_STATE + lane];
    float dtd = fminf(fmaxf(expf(log_dt[d]), 1e-3f), 1e-1f);

    float h  = 0.f;
    float xv = __ldg(&x[d]);
    float gv = __ldg(&gate[d]);

    for (int t = 0; t < S_LEN; t++) {
        float xn = 0.f, gn = 0.f;
        if (t + 1 < S_LEN) {
            xn = __ldg(&x[(t + 1) * D_DIM + d]);
            gn = __ldg(&gate[(t + 1) * D_DIM + d]);
        }
        float p0 = 0.f, p1 = 0.f, p2 = 0.f, p3 = 0.f;
#pragma unroll
        for (int m = 0; m < 4; m++) {
            p0 = fmaf(Arow[m],      __shfl_sync(FULLM, h, m,      16), p0);
            p1 = fmaf(Arow[m + 4],  __shfl_sync(FULLM, h, m + 4,  16), p1);
            p2 = fmaf(Arow[m + 8],  __shfl_sync(FULLM, h, m + 8,  16), p2);
            p3 = fmaf(Arow[m + 12], __shfl_sync(FULLM, h, m + 12, 16), p3);
        }
        float acc = (p0 + p1) + (p2 + p3);
        float sc  = (acc + xv * Bn) * dtd;
        float gm  = (fabsf(sc) > SPIKE) ? gv : 0.f;
        h = fmaf(sc, gm, h);

        float pr = h * Cn;
#pragma unroll
        for (int off = 8; off; off >>= 1)
            pr += __shfl_xor_sync(FULLM, pr, off, 16);
        if (lane == 0) Hout[t * D_DIM + d] = xv + pr;

        xv = xn; gv = gn;
    }
}

// ---------------------------------------------------------------------------
// Per-row: radix-select kk-th largest |score|, local+sparse mask, softmax.
// Row in registers; per-warp histograms; warp-0 shuffle suffix-scan.
// Writes only the banded region read by PV (j < (i&~63)+192).
// ---------------------------------------------------------------------------
__global__ __launch_bounds__(256)
void mask_softmax_kernel(float* __restrict__ scores)
{
    int i  = blockIdx.x;
    int hd = blockIdx.y;
    float* row = scores + ((size_t)hd * S_LEN + i) * S_LEN;

    __shared__ int   hist[8][256];
    __shared__ int   red[256];
    __shared__ int   sh_sel[2];
    __shared__ float fred[8];

    int tid = threadIdx.x, lane = tid & 31, wid = tid >> 5;

    float r[8]; unsigned u[8];
    {
        float4 v0 = *(const float4*)&row[tid * 8];
        float4 v1 = *(const float4*)&row[tid * 8 + 4];
        r[0] = v0.x; r[1] = v0.y; r[2] = v0.z; r[3] = v0.w;
        r[4] = v1.x; r[5] = v1.y; r[6] = v1.z; r[7] = v1.w;
    }
#pragma unroll
    for (int e = 0; e < 8; e++) u[e] = __float_as_uint(fabsf(r[e]));

    unsigned prefix = 0;
    int kneed = KK;
#pragma unroll
    for (int byte = 3; byte >= 0; --byte) {
        for (int b = lane; b < 256; b += 32) hist[wid][b] = 0;
        __syncthreads();
        unsigned pm = (byte == 3) ? 0u : (0xFFFFFFFFu << (8 * (byte + 1)));
#pragma unroll
        for (int e = 0; e < 8; e++)
            if ((u[e] & pm) == prefix)
                atomicAdd(&hist[wid][(u[e] >> (8 * byte)) & 255], 1);
        __syncthreads();
        int cnt = 0;
#pragma unroll
        for (int w = 0; w < 8; w++) cnt += hist[w][tid];
        red[tid] = cnt;
        __syncthreads();
        if (wid == 0) {
            int v[8], cum[8], s = 0;
#pragma unroll
            for (int e = 0; e < 8; e++) {
                v[e] = red[255 - (lane * 8 + e)];
                s += v[e];
                cum[e] = s;
            }
            int incl = s;
#pragma unroll
            for (int off = 1; off < 32; off <<= 1) {
                int t2 = __shfl_up_sync(FULLM, incl, off);
                if (lane >= off) incl += t2;
            }
            int excl = incl - s;
            bool has = (excl + cum[7]) >= kneed && excl < kneed;
            unsigned bal = __ballot_sync(FULLM, has);
            int fl = __ffs(bal) - 1;
            if (lane == fl) {
                int e = 0;
                while (excl + cum[e] < kneed) e++;
                sh_sel[0] = 255 - (lane * 8 + e);
                sh_sel[1] = kneed - (excl + cum[e] - v[e]);
            }
        }
        __syncthreads();
        prefix |= ((unsigned)sh_sel[0]) << (8 * byte);
        kneed = sh_sel[1];
        __syncthreads();
    }
    unsigned T = prefix;

    int jmax = i + WINDOW;
    float m = -INFINITY;
    float sv[8];
#pragma unroll
    for (int e = 0; e < 8; e++) {
        int j = tid * 8 + e;
        bool keep = (j <= jmax) && (u[e] >= T);
        sv[e] = keep ? r[e] : -INFINITY;
        m = fmaxf(m, sv[e]);
    }
#pragma unroll
    for (int off = 16; off; off >>= 1)
        m = fmaxf(m, __shfl_xor_sync(FULLM, m, off));
    if (lane == 0) fred[wid] = m;
    __syncthreads();
    float mm = -INFINITY;
#pragma unroll
    for (int w = 0; w < 8; w++) mm = fmaxf(mm, fred[w]);
    __syncthreads();

    float z = 0.f;
    float ex[8];
#pragma unroll
    for (int e = 0; e < 8; e++) {
        ex[e] = (sv[e] == -INFINITY) ? 0.f : __expf(sv[e] - mm);
        z += ex[e];
    }
#pragma unroll
    for (int off = 16; off; off >>= 1)
        z += __shfl_xor_sync(FULLM, z, off);
    if (lane == 0) fred[wid] = z;
    __syncthreads();
    float zz = 0.f;
#pragma unroll
    for (int w = 0; w < 8; w++) zz += fred[w];
    float inv = (zz > 0.f) ? 1.f / zz : 0.f;

    // PV (BM=64, band=192) only reads j < (i&~63)+192; rest stays unread.
    int limit = (i & ~63) + 192;
    if (tid * 8 < limit) {
        float4 o0 = make_float4(ex[0] * inv, ex[1] * inv, ex[2] * inv, ex[3] * inv);
        float4 o1 = make_float4(ex[4] * inv, ex[5] * inv, ex[6] * inv, ex[7] * inv);
        *(float4*)&row[tid * 8]     = o0;
        *(float4*)&row[tid * 8 + 4] = o1;
    }
}

// ---------------------------------------------------------------------------
// Launch
// ---------------------------------------------------------------------------
extern "C" void kernel_launch(void* const* d_in, const int* in_sizes, int n_in,
                              void* d_out, int out_size)
{
    const float* x      = (const float*)d_in[0];
    const float* Amat   = (const float*)d_in[1];
    const float* Bm     = (const float*)d_in[2];
    const float* Cm     = (const float*)d_in[3];
    const float* log_dt = (const float*)d_in[4];
    const float* Wg = (const float*)d_in[5];  const float* bg = (const float*)d_in[6];
    const float* Wq = (const float*)d_in[7];  const float* bq = (const float*)d_in[8];
    const float* Wk = (const float*)d_in[9];  const float* bk = (const float*)d_in[10];
    const float* Wv = (const float*)d_in[11]; const float* bv = (const float*)d_in[12];
    const float* Wd = (const float*)d_in[13]; const float* bd = (const float*)d_in[14];
    float* out = (float*)d_out;

    float *gate, *H, *Q, *K, *V, *ctx, *scores;
    cudaGetSymbolAddress((void**)&gate,   g_gate);
    cudaGetSymbolAddress((void**)&H,      g_H);
    cudaGetSymbolAddress((void**)&Q,      g_Q);
    cudaGetSymbolAddress((void**)&K,      g_K);
    cudaGetSymbolAddress((void**)&V,      g_V);
    cudaGetSymbolAddress((void**)&ctx,    g_ctx);
    cudaGetSymbolAddress((void**)&scores, g_scores);

    dim3 blk(256);

    // 1) gate = sigmoid(X Wg^T + bg)
    {
        dim3 grid(D_DIM / 64, S_LEN / 64, 1);
        gemm_tc<true, 2, 1><<<grid, blk>>>(x, Wg, Wg, Wg, bg, bg, bg,
            gate, gate, gate,
            D_DIM, D_DIM, D_DIM, D_DIM, 0, 0, 0, 1.f, 0, D_DIM / 64);
    }
    // 2) SSM scan -> H = x + y
    ssm_kernel<<<D_DIM / 8, 128>>>(x, gate, Amat, Bm, Cm, log_dt, H);

    // 3) Fused Q,K,V projections (B/C selected per x-block)
    {
        dim3 grid(3 * D_DIM / 64, S_LEN / 64, 1);
        gemm_tc<true, 1, 1><<<grid, blk>>>(H, Wq, Wk, Wv, bq, bk, bv,
            Q, K, V,
            D_DIM, D_DIM, D_DIM, D_DIM, 0, 0, 0, 1.f, 0, D_DIM / 64);
    }
    // 4) scores[h] = Q_h K_h^T / 8
    {
        dim3 grid(S_LEN / 64, S_LEN / 64, N_HEADS);
        gemm_tc<true, 0, 1><<<grid, blk>>>(Q, K, K, K, nullptr, nullptr, nullptr,
            scores, scores, scores,
            DH, D_DIM, D_DIM, S_LEN,
            DH, DH, (long)S_LEN * S_LEN, 0.125f, 0, S_LEN / 64);
    }
    // 5) per-row top-k select + masks + softmax (in place, banded writes)
    {
        dim3 grid(S_LEN, N_HEADS);
        mask_softmax_kernel<<<grid, blk>>>(scores);
    }
    // 6) ctx[h] = P_h V_h   (banded, split-K=2, atomic adds)
    {
        cudaMemsetAsync(ctx, 0, (size_t)S_LEN * D_DIM * sizeof(float));
        dim3 grid(DH / 64, S_LEN / 64, N_HEADS * 2);
        gemm_tc<false, 3, 2><<<grid, blk>>>(scores, V, V, V, nullptr, nullptr, nullptr,
            ctx, ctx, ctx,
            S_LEN, S_LEN, D_DIM, D_DIM,
            (long)S_LEN * S_LEN, DH, DH, 1.f, 64 + WINDOW, DH / 64);
    }
    // 7) out = ctx Wd^T + bd
    {
        dim3 grid(D_DIM / 64, S_LEN / 64, 1);
        gemm_tc<true, 1, 1><<<grid, blk>>>(ctx, Wd, Wd, Wd, bd, bd, bd,
            out, out, out,
            D_DIM, D_DIM, D_DIM, D_DIM, 0, 0, 0, 1.f, 0, D_DIM / 64);
    }
}